// round 11
// baseline (speedup 1.0000x reference)
#include <cuda_runtime.h>
#include <cstdint>

// ---------------------------------------------------------------------------
// EncoderGRU: bidirectional GRU, SEQ=4096, HIDDEN=EMBED=1024.
//
//   Phase 1+2 (one kernel): GI[t] = w_ih @ emb[tok[t]] + b_ih, fp32 SIMT GEMM,
//            inline token prep + recurrent-state reset by block (0,0).
//   Phase 3: persistent kernel, 128 CTAs (64 fwd / 64 bwd), each CTA owns 16
//            hidden units (48 w_hh rows; 4/warp in registers, 2/warp in smem).
//
//   Sync (NEW): h is stored as packed {f32 value, u32 step-tag} 8-byte words
//   (single ST.E.64 -> atomic). Consumers poll the h buffer directly: the
//   load that detects readiness IS the data fetch (one L2 leg instead of
//   counter-detect + h-fetch). No fences anywhere: value and tag share one
//   atomic word, so there is no inter-address ordering to enforce.
//   Ring-2 buffer safety: all tags == s-1 on the read buffer implies every
//   CTA completed step s-1, hence finished reading the buffer that step s+1
//   overwrites (a CTA writes its tag only after consuming its h inputs).
// ---------------------------------------------------------------------------

#define VOCAB   50257
#define HID     1024
#define SEQ     4096
#define NROWS   (SEQ + 2)       // 4098: +SOS row, +EOS row
#define GATES   3072

#define NCTA    128             // persistent grid (1 CTA/SM)
#define UNITS   16              // hidden units per CTA (64 CTAs/dir * 16 = 1024)
#define RPC     48              // weight rows per CTA (3 gates * 16 units)
#define GT      256             // threads in recurrent kernel
#define RPW     6               // rows per warp (8 warps * 6 = 48)
#define RREG    4               // rows per warp held in registers
#define RSM     2               // rows per warp streamed from smem (RPW-RREG)

// ---- global scratch (allocation-free: __device__ globals) ----
__device__ __align__(16) float g_GI[(size_t)NROWS * GATES];     // ~50 MB
__device__ __align__(16) uint2 g_ht[2][2][HID];                 // [dir][buf][unit]={val,tag}

// Calibrated busy-wait: no memory traffic, bounded duration (SM clock cycles).
__device__ __forceinline__ void spin_cycles(long long n) {
    long long lim = clock64() + n;
    while (clock64() < lim) { }
}

// ---------------------------------------------------------------------------
// Phase 1+2: GI GEMM with inline token prep + state reset.
// C[m][n] = sum_k emb[tok[m]][k] * w_ih[n][k] + b_ih[n]
// BM=BN=128, BK=8, 256 threads, 8x8 microtile per thread.
// ---------------------------------------------------------------------------
#define BM 128
#define BN 128
#define BK 8

__global__ void __launch_bounds__(256) gi_gemm_kernel(
    const void*  __restrict__ tok_raw,
    const float* __restrict__ emb,
    const float* __restrict__ w_ih,
    const float* __restrict__ b_ih) {

    __shared__ float As[BK][BM];
    __shared__ float Bs[BK][BN];
    __shared__ int   mode64_sh;

    const int tid  = threadIdx.x;
    const int m0   = blockIdx.y * BM;
    const int n0   = blockIdx.x * BN;
    const int lrow = tid >> 1;          // 0..127
    const int lk   = (tid & 1) * 4;     // 0 or 4
    const int tx   = tid & 15;
    const int ty   = tid >> 4;

    // state reset (fresh every launch / graph replay) -- block (0,0) only.
    // values = 0 (initial h), tags = 0xFFFFFFFF (never equals a step 0..4095)
    if (blockIdx.x == 0 && blockIdx.y == 0) {
        uint2* ht = (uint2*)g_ht;
        for (int i = tid; i < 2 * 2 * HID; i += 256)
            ht[i] = make_uint2(0u, 0xFFFFFFFFu);
    }

    // token dtype detection (per block; 8 loads, trivial)
    if (tid == 0) {
        // Genuine int64 tokens: every value < VOCAB (high word 0).
        // int32 data misread as int64: some 64-bit word >= VOCAB w.h.p.
        const unsigned long long* p = (const unsigned long long*)tok_raw;
        int m = 1;
        #pragma unroll
        for (int i = 0; i < 8; i++)
            if (p[i] >= (unsigned long long)VOCAB) m = 0;
        mode64_sh = m;
    }
    __syncthreads();
    const int mode64 = mode64_sh;

    // inline token fetch for this block's A row
    const int m = m0 + lrow;
    const float* arow_ptr = nullptr;
    if (m < NROWS) {
        int tok;
        if (m == SEQ)          tok = 0;   // SOS
        else if (m == SEQ + 1) tok = 1;   // EOS
        else tok = mode64 ? (int)((const long long*)tok_raw)[m]
                          : ((const int*)tok_raw)[m];
        arow_ptr = emb + (size_t)tok * HID;
    }
    const float* brow_ptr = w_ih + (size_t)(n0 + lrow) * HID;

    float acc[8][8];
    #pragma unroll
    for (int i = 0; i < 8; i++)
        #pragma unroll
        for (int j = 0; j < 8; j++) acc[i][j] = 0.f;

    for (int k0 = 0; k0 < HID; k0 += BK) {
        float4 a4 = make_float4(0.f, 0.f, 0.f, 0.f);
        if (arow_ptr) a4 = *(const float4*)(arow_ptr + k0 + lk);
        float4 b4 = *(const float4*)(brow_ptr + k0 + lk);
        As[lk + 0][lrow] = a4.x; As[lk + 1][lrow] = a4.y;
        As[lk + 2][lrow] = a4.z; As[lk + 3][lrow] = a4.w;
        Bs[lk + 0][lrow] = b4.x; Bs[lk + 1][lrow] = b4.y;
        Bs[lk + 2][lrow] = b4.z; Bs[lk + 3][lrow] = b4.w;
        __syncthreads();

        #pragma unroll
        for (int kk = 0; kk < BK; kk++) {
            float ra[8], rb[8];
            *(float4*)&ra[0] = *(const float4*)&As[kk][ty * 8];
            *(float4*)&ra[4] = *(const float4*)&As[kk][ty * 8 + 4];
            *(float4*)&rb[0] = *(const float4*)&Bs[kk][tx * 8];
            *(float4*)&rb[4] = *(const float4*)&Bs[kk][tx * 8 + 4];
            #pragma unroll
            for (int i = 0; i < 8; i++)
                #pragma unroll
                for (int j = 0; j < 8; j++)
                    acc[i][j] += ra[i] * rb[j];
        }
        __syncthreads();
    }

    float bias[8];
    *(float4*)&bias[0] = *(const float4*)(b_ih + n0 + tx * 8);
    *(float4*)&bias[4] = *(const float4*)(b_ih + n0 + tx * 8 + 4);

    #pragma unroll
    for (int i = 0; i < 8; i++) {
        int mm = m0 + ty * 8 + i;
        if (mm < NROWS) {
            float* gp = g_GI + (size_t)mm * GATES + n0 + tx * 8;
            float4 v0 = make_float4(acc[i][0] + bias[0], acc[i][1] + bias[1],
                                    acc[i][2] + bias[2], acc[i][3] + bias[3]);
            float4 v1 = make_float4(acc[i][4] + bias[4], acc[i][5] + bias[5],
                                    acc[i][6] + bias[6], acc[i][7] + bias[7]);
            *(float4*)gp       = v0;
            *(float4*)(gp + 4) = v1;
        }
    }
}

// ---------------------------------------------------------------------------
// Phase 3: persistent recurrent kernel (tagged-h sync, fence-free).
// Weight rows per warp: rows 0..3 in registers, rows 4..5 in smem.
// Global row for local row rr (0..47): ((rr>>4)<<10) + u0 + (rr&15).
// ---------------------------------------------------------------------------
__global__ void __launch_bounds__(GT, 1) gru_seq_kernel(
    const float* __restrict__ w_hh,
    const float* __restrict__ b_hh,
    float* __restrict__ out) {

    extern __shared__ float smem[];
    float* wsh  = smem;                 // 16 rows (2/warp) * HID
    float* bsh  = smem + (RSM * 8) * HID;   // RPC biases
    float* sums = bsh + RPC;            // RPC partial sums

    const int cta  = blockIdx.x;
    const int dir  = cta >> 6;          // 0 = forward, 1 = backward
    const int lcta = cta & 63;
    const int u0   = lcta * UNITS;
    const int warp = threadIdx.x >> 5;
    const int lane = threadIdx.x & 31;

    // --- smem rows: local rows {w*6+4, w*6+5} stored at smem row (w*2 + sub)
    for (int i = threadIdx.x; i < RSM * 8 * HID; i += GT) {
        int mrow = i >> 10;             // 0..15
        int c    = i & (HID - 1);
        int rr   = (mrow >> 1) * RPW + RREG + (mrow & 1);
        int grow = ((rr >> 4) << 10) + u0 + (rr & 15);
        wsh[i] = w_hh[(size_t)grow * HID + c];
    }
    if (threadIdx.x < RPC) {
        int rr = threadIdx.x;
        bsh[rr] = b_hh[((rr >> 4) << 10) + u0 + (rr & 15)];
    }

    // --- register rows: warp's local rows 0..3, this lane's 32 columns
    float4 wreg[RREG][8];
    #pragma unroll
    for (int r = 0; r < RREG; r++) {
        const int rr   = warp * RPW + r;
        const int grow = ((rr >> 4) << 10) + u0 + (rr & 15);
        const float* gw = w_hh + (size_t)grow * HID + lane * 4;
        #pragma unroll
        for (int j = 0; j < 8; j++)
            wreg[r][j] = *(const float4*)(gw + j * 128);
    }
    __syncthreads();

    const float* wp = wsh + (warp * RSM) * HID + lane * 4;  // smem rows 4..5

    float hprev = 0.f;                  // held by threads < UNITS only

    for (int s = 0; s <= SEQ; s++) {
        const int t     = dir ? (SEQ - s) : (s - 1);
        const int girow = (s == 0) ? (SEQ + dir) : t;

        // gi prefetch (independent of h; overlaps the poll below)
        float gir = 0.f, giz = 0.f, gin = 0.f;
        if (threadIdx.x < UNITS) {
            const float* gp = g_GI + (size_t)girow * GATES + u0 + threadIdx.x;
            gir = __ldg(gp);
            giz = __ldg(gp + HID);
            gin = __ldg(gp + 2 * HID);
        }

        // --- load h: tagged words, the load itself is the sync. Lane needs
        // units lane*4+k+j*128 (k=0..3, j=0..7) = 16 uint4 (2 units each).
        float4 h4[8];
        if (s > 0) {
            const unsigned need = (unsigned)(s - 1);
            const uint4* hp4 = (const uint4*)(&g_ht[dir][s & 1][0]) + lane * 2;
            for (;;) {
                unsigned bad = 0u;
                #pragma unroll
                for (int j = 0; j < 8; j++) {
                    uint4 q0 = __ldcg(hp4 + j * 64);
                    uint4 q1 = __ldcg(hp4 + j * 64 + 1);
                    bad |= (q0.y ^ need) | (q0.w ^ need)
                         | (q1.y ^ need) | (q1.w ^ need);
                    h4[j] = make_float4(__uint_as_float(q0.x),
                                        __uint_as_float(q0.z),
                                        __uint_as_float(q1.x),
                                        __uint_as_float(q1.z));
                }
                if (__all_sync(0xffffffffu, bad == 0u)) break;
                spin_cycles(200);
            }
        } else {
            #pragma unroll
            for (int j = 0; j < 8; j++)
                h4[j] = make_float4(0.f, 0.f, 0.f, 0.f);
        }

        // 6 dot products per warp: rows 0..3 from registers, 4..5 from smem
        float acc[RPW] = {0.f, 0.f, 0.f, 0.f, 0.f, 0.f};
        #pragma unroll
        for (int j = 0; j < 8; j++) {
            const float4 hv = h4[j];
            #pragma unroll
            for (int r = 0; r < RREG; r++) {
                const float4 wv = wreg[r][j];
                acc[r] += hv.x * wv.x;
                acc[r] += hv.y * wv.y;
                acc[r] += hv.z * wv.z;
                acc[r] += hv.w * wv.w;
            }
            #pragma unroll
            for (int r = 0; r < RSM; r++) {
                const float4 wv = *(const float4*)(wp + r * HID + j * 128);
                acc[RREG + r] += hv.x * wv.x;
                acc[RREG + r] += hv.y * wv.y;
                acc[RREG + r] += hv.z * wv.z;
                acc[RREG + r] += hv.w * wv.w;
            }
        }
        #pragma unroll
        for (int r = 0; r < RPW; r++) {
            float v = acc[r];
            v += __shfl_xor_sync(0xffffffffu, v, 16);
            v += __shfl_xor_sync(0xffffffffu, v, 8);
            v += __shfl_xor_sync(0xffffffffu, v, 4);
            v += __shfl_xor_sync(0xffffffffu, v, 2);
            v += __shfl_xor_sync(0xffffffffu, v, 1);
            if (lane == 0) sums[warp * RPW + r] = v;
        }
        __syncthreads();                // sums ready (all h loads consumed)

        if (threadIdx.x < UNITS) {
            const int i = threadIdx.x;
            const int u = u0 + i;
            // fast gates: __expf (MUFU) + approx division
            float ar = gir + sums[i]      + bsh[i];
            float az = giz + sums[16 + i] + bsh[16 + i];
            float rg = __fdividef(1.f, 1.f + __expf(-ar));
            float zg = __fdividef(1.f, 1.f + __expf(-az));
            float an = gin + rg * (sums[32 + i] + bsh[32 + i]);
            float en = __expf(-2.f * an);
            float ng = __fdividef(1.f - en, 1.f + en);   // tanh(an)
            float hn = (1.f - zg) * ng + zg * hprev;
            hprev = hn;
            // publish: value+tag in ONE atomic 8-byte word, no fence needed.
            unsigned long long pv =
                ((unsigned long long)(unsigned)s << 32)
                | (unsigned long long)__float_as_uint(hn);
            asm volatile("st.global.cg.b64 [%0], %1;"
                         :: "l"(&g_ht[dir][(s + 1) & 1][u]), "l"(pv)
                         : "memory");
            if (s >= 1) {
                // hiddens[t] = [hs_f[t] | hs_b[t]], after h_b (1024 floats)
                out[(size_t)HID + (size_t)t * (2 * HID) + dir * HID + u] = hn;
                if (dir == 1 && t == 0) out[u] = hn;   // h_b = hs_b[0]
            }
        }
        __syncthreads();                // protect sums[] reuse next iteration
    }
}

// ---------------------------------------------------------------------------
// launch
// ---------------------------------------------------------------------------
extern "C" void kernel_launch(void* const* d_in, const int* in_sizes, int n_in,
                              void* d_out, int out_size) {
    const void*  tokens = d_in[0];
    const float* emb    = (const float*)d_in[1];
    const float* w_ih   = (const float*)d_in[2];
    const float* w_hh   = (const float*)d_in[3];
    const float* b_ih   = (const float*)d_in[4];
    const float* b_hh   = (const float*)d_in[5];
    float* out = (float*)d_out;

    const int smem_bytes = (RSM * 8 * HID + 2 * RPC + 16) * (int)sizeof(float);
    cudaFuncSetAttribute(gru_seq_kernel,
                         cudaFuncAttributeMaxDynamicSharedMemorySize,
                         smem_bytes);

    dim3 ggrid(GATES / BN, (NROWS + BM - 1) / BM);
    gi_gemm_kernel<<<ggrid, 256>>>(tokens, emb, w_ih, b_ih);

    gru_seq_kernel<<<NCTA, GT, smem_bytes>>>(w_hh, b_hh, out);
}

// round 12
// speedup vs baseline: 1.2906x; 1.2906x over previous
#include <cuda_runtime.h>
#include <cstdint>

// ---------------------------------------------------------------------------
// EncoderGRU: bidirectional GRU, SEQ=4096, HIDDEN=EMBED=1024.
//
//   Phase 1+2 (one kernel): GI[t] = w_ih @ emb[tok[t]] + b_ih, fp32 SIMT GEMM,
//            inline token prep + recurrent-state reset by block (0,0).
//   Phase 3: persistent kernel, 128 CTAs (64 fwd / 64 bwd), each CTA owns 16
//            hidden units (48 w_hh rows; 4/warp in registers, 2/warp in smem).
//            Sync protocol: round-10 shape (proven, fastest so far) with the
//            fences fused into the atomics:
//              producer: gates -> stcg h -> __syncthreads ->
//                        thread0 red.release.gpu (cumulative: covers the
//                        CTA's h stores via the bar) ; out[] stores AFTER
//                        the publish (off the release drain set).
//              consumer: every thread polls with ld.acquire.gpu (the acquire
//                        IS the ordering; no MEMBAR) + ~350cyc clock-spin
//                        backoff between polls.
// ---------------------------------------------------------------------------

#define VOCAB   50257
#define HID     1024
#define SEQ     4096
#define NROWS   (SEQ + 2)       // 4098: +SOS row, +EOS row
#define GATES   3072

#define NCTA    128             // persistent grid (1 CTA/SM)
#define UNITS   16              // hidden units per CTA (64 CTAs/dir * 16 = 1024)
#define RPC     48              // weight rows per CTA (3 gates * 16 units)
#define GT      256             // threads in recurrent kernel
#define RPW     6               // rows per warp (8 warps * 6 = 48)
#define RREG    4               // rows per warp held in registers
#define RSM     2               // rows per warp streamed from smem (RPW-RREG)

// ---- global scratch (allocation-free: __device__ globals) ----
__device__ __align__(16)  float g_GI[(size_t)NROWS * GATES];    // ~50 MB
__device__ __align__(16)  float g_h[2][2][HID];                 // [dir][buf][unit]
__device__ __align__(128) int   g_cnt[2][32];                   // one 128B line per dir

// acquire-load: ordering + data in one instruction (pairs with red.release)
__device__ __forceinline__ int ld_acq(const int* p) {
    int v;
    asm volatile("ld.acquire.gpu.global.b32 %0, [%1];"
                 : "=r"(v) : "l"(p) : "memory");
    return v;
}
// release-reduction: publishes +1 with release semantics (cumulative through
// the preceding bar.sync -> covers the CTA's prior h stores)
__device__ __forceinline__ void red_rel_add(int* p) {
    asm volatile("red.release.gpu.global.add.u32 [%0], 1;"
                 :: "l"(p) : "memory");
}

// Calibrated busy-wait: no memory traffic, bounded duration (SM clock cycles).
__device__ __forceinline__ void spin_cycles(long long n) {
    long long lim = clock64() + n;
    while (clock64() < lim) { }
}

// ---------------------------------------------------------------------------
// Phase 1+2: GI GEMM with inline token prep + state reset.
// C[m][n] = sum_k emb[tok[m]][k] * w_ih[n][k] + b_ih[n]
// BM=BN=128, BK=8, 256 threads, 8x8 microtile per thread.
// ---------------------------------------------------------------------------
#define BM 128
#define BN 128
#define BK 8

__global__ void __launch_bounds__(256) gi_gemm_kernel(
    const void*  __restrict__ tok_raw,
    const float* __restrict__ emb,
    const float* __restrict__ w_ih,
    const float* __restrict__ b_ih) {

    __shared__ float As[BK][BM];
    __shared__ float Bs[BK][BN];
    __shared__ int   mode64_sh;

    const int tid  = threadIdx.x;
    const int m0   = blockIdx.y * BM;
    const int n0   = blockIdx.x * BN;
    const int lrow = tid >> 1;          // 0..127
    const int lk   = (tid & 1) * 4;     // 0 or 4
    const int tx   = tid & 15;
    const int ty   = tid >> 4;

    // state reset (fresh every launch / graph replay) -- block (0,0) only
    if (blockIdx.x == 0 && blockIdx.y == 0) {
        for (int i = tid; i < 2 * 2 * HID; i += 256) ((float*)g_h)[i] = 0.f;
        if (tid < 64) ((int*)g_cnt)[tid] = 0;
    }

    // token dtype detection (per block; 8 loads, trivial)
    if (tid == 0) {
        // Genuine int64 tokens: every value < VOCAB (high word 0).
        // int32 data misread as int64: some 64-bit word >= VOCAB w.h.p.
        const unsigned long long* p = (const unsigned long long*)tok_raw;
        int m = 1;
        #pragma unroll
        for (int i = 0; i < 8; i++)
            if (p[i] >= (unsigned long long)VOCAB) m = 0;
        mode64_sh = m;
    }
    __syncthreads();
    const int mode64 = mode64_sh;

    // inline token fetch for this block's A row
    const int m = m0 + lrow;
    const float* arow_ptr = nullptr;
    if (m < NROWS) {
        int tok;
        if (m == SEQ)          tok = 0;   // SOS
        else if (m == SEQ + 1) tok = 1;   // EOS
        else tok = mode64 ? (int)((const long long*)tok_raw)[m]
                          : ((const int*)tok_raw)[m];
        arow_ptr = emb + (size_t)tok * HID;
    }
    const float* brow_ptr = w_ih + (size_t)(n0 + lrow) * HID;

    float acc[8][8];
    #pragma unroll
    for (int i = 0; i < 8; i++)
        #pragma unroll
        for (int j = 0; j < 8; j++) acc[i][j] = 0.f;

    for (int k0 = 0; k0 < HID; k0 += BK) {
        float4 a4 = make_float4(0.f, 0.f, 0.f, 0.f);
        if (arow_ptr) a4 = *(const float4*)(arow_ptr + k0 + lk);
        float4 b4 = *(const float4*)(brow_ptr + k0 + lk);
        As[lk + 0][lrow] = a4.x; As[lk + 1][lrow] = a4.y;
        As[lk + 2][lrow] = a4.z; As[lk + 3][lrow] = a4.w;
        Bs[lk + 0][lrow] = b4.x; Bs[lk + 1][lrow] = b4.y;
        Bs[lk + 2][lrow] = b4.z; Bs[lk + 3][lrow] = b4.w;
        __syncthreads();

        #pragma unroll
        for (int kk = 0; kk < BK; kk++) {
            float ra[8], rb[8];
            *(float4*)&ra[0] = *(const float4*)&As[kk][ty * 8];
            *(float4*)&ra[4] = *(const float4*)&As[kk][ty * 8 + 4];
            *(float4*)&rb[0] = *(const float4*)&Bs[kk][tx * 8];
            *(float4*)&rb[4] = *(const float4*)&Bs[kk][tx * 8 + 4];
            #pragma unroll
            for (int i = 0; i < 8; i++)
                #pragma unroll
                for (int j = 0; j < 8; j++)
                    acc[i][j] += ra[i] * rb[j];
        }
        __syncthreads();
    }

    float bias[8];
    *(float4*)&bias[0] = *(const float4*)(b_ih + n0 + tx * 8);
    *(float4*)&bias[4] = *(const float4*)(b_ih + n0 + tx * 8 + 4);

    #pragma unroll
    for (int i = 0; i < 8; i++) {
        int mm = m0 + ty * 8 + i;
        if (mm < NROWS) {
            float* gp = g_GI + (size_t)mm * GATES + n0 + tx * 8;
            float4 v0 = make_float4(acc[i][0] + bias[0], acc[i][1] + bias[1],
                                    acc[i][2] + bias[2], acc[i][3] + bias[3]);
            float4 v1 = make_float4(acc[i][4] + bias[4], acc[i][5] + bias[5],
                                    acc[i][6] + bias[6], acc[i][7] + bias[7]);
            *(float4*)gp       = v0;
            *(float4*)(gp + 4) = v1;
        }
    }
}

// ---------------------------------------------------------------------------
// Phase 3: persistent recurrent kernel.
// Weight rows per warp: rows 0..3 in registers, rows 4..5 in smem.
// Global row for local row rr (0..47): ((rr>>4)<<10) + u0 + (rr&15).
// ---------------------------------------------------------------------------
__global__ void __launch_bounds__(GT, 1) gru_seq_kernel(
    const float* __restrict__ w_hh,
    const float* __restrict__ b_hh,
    float* __restrict__ out) {

    extern __shared__ float smem[];
    float* wsh  = smem;                 // 16 rows (2/warp) * HID
    float* bsh  = smem + (RSM * 8) * HID;   // RPC biases
    float* sums = bsh + RPC;            // RPC partial sums

    const int cta  = blockIdx.x;
    const int dir  = cta >> 6;          // 0 = forward, 1 = backward
    const int lcta = cta & 63;
    const int u0   = lcta * UNITS;
    const int warp = threadIdx.x >> 5;
    const int lane = threadIdx.x & 31;

    // --- smem rows: local rows {w*6+4, w*6+5} stored at smem row (w*2 + sub)
    for (int i = threadIdx.x; i < RSM * 8 * HID; i += GT) {
        int mrow = i >> 10;             // 0..15
        int c    = i & (HID - 1);
        int rr   = (mrow >> 1) * RPW + RREG + (mrow & 1);
        int grow = ((rr >> 4) << 10) + u0 + (rr & 15);
        wsh[i] = w_hh[(size_t)grow * HID + c];
    }
    if (threadIdx.x < RPC) {
        int rr = threadIdx.x;
        bsh[rr] = b_hh[((rr >> 4) << 10) + u0 + (rr & 15)];
    }

    // --- register rows: warp's local rows 0..3, this lane's 32 columns
    float4 wreg[RREG][8];
    #pragma unroll
    for (int r = 0; r < RREG; r++) {
        const int rr   = warp * RPW + r;
        const int grow = ((rr >> 4) << 10) + u0 + (rr & 15);
        const float* gw = w_hh + (size_t)grow * HID + lane * 4;
        #pragma unroll
        for (int j = 0; j < 8; j++)
            wreg[r][j] = *(const float4*)(gw + j * 128);
    }
    __syncthreads();

    const float* wp = wsh + (warp * RSM) * HID + lane * 4;  // smem rows 4..5
    int* cnt_p = &g_cnt[dir][0];

    float hprev = 0.f;                  // held by threads < UNITS only

    for (int s = 0; s <= SEQ; s++) {
        const int t     = dir ? (SEQ - s) : (s - 1);
        const int girow = (s == 0) ? (SEQ + dir) : t;

        // gi prefetch (independent of h; overlaps the poll below)
        float gir = 0.f, giz = 0.f, gin = 0.f;
        if (threadIdx.x < UNITS) {
            const float* gp = g_GI + (size_t)girow * GATES + u0 + threadIdx.x;
            gir = __ldg(gp);
            giz = __ldg(gp + HID);
            gin = __ldg(gp + 2 * HID);
        }

        // Wait until all 64 CTAs of this direction finished step s-1.
        // EVERY thread polls with an ACQUIRE load (broadcast 4B sector):
        // the load that detects readiness also provides the ordering for the
        // subsequent h reads -- no separate MEMBAR. ~350cyc spin backoff
        // keeps the hot sector below L2 slice capacity.
        if (s > 0) {
            const int need = s << 6;    // 64 * s
            if (ld_acq(cnt_p) < need) {
                do { spin_cycles(350); } while (ld_acq(cnt_p) < need);
            }
        }

        // load broadcast h (L2: written by other SMs last step)
        const float4* hp = (const float4*)(&g_h[dir][s & 1][0]) + lane;
        float4 h4[8];
        #pragma unroll
        for (int j = 0; j < 8; j++) h4[j] = __ldcg(hp + 32 * j);

        // 6 dot products per warp: rows 0..3 from registers, 4..5 from smem
        float acc[RPW] = {0.f, 0.f, 0.f, 0.f, 0.f, 0.f};
        #pragma unroll
        for (int j = 0; j < 8; j++) {
            const float4 hv = h4[j];
            #pragma unroll
            for (int r = 0; r < RREG; r++) {
                const float4 wv = wreg[r][j];
                acc[r] += hv.x * wv.x;
                acc[r] += hv.y * wv.y;
                acc[r] += hv.z * wv.z;
                acc[r] += hv.w * wv.w;
            }
            #pragma unroll
            for (int r = 0; r < RSM; r++) {
                const float4 wv = *(const float4*)(wp + r * HID + j * 128);
                acc[RREG + r] += hv.x * wv.x;
                acc[RREG + r] += hv.y * wv.y;
                acc[RREG + r] += hv.z * wv.z;
                acc[RREG + r] += hv.w * wv.w;
            }
        }
        #pragma unroll
        for (int r = 0; r < RPW; r++) {
            float v = acc[r];
            v += __shfl_xor_sync(0xffffffffu, v, 16);
            v += __shfl_xor_sync(0xffffffffu, v, 8);
            v += __shfl_xor_sync(0xffffffffu, v, 4);
            v += __shfl_xor_sync(0xffffffffu, v, 2);
            v += __shfl_xor_sync(0xffffffffu, v, 1);
            if (lane == 0) sums[warp * RPW + r] = v;
        }
        __syncthreads();                // sums ready

        float hn = 0.f;
        if (threadIdx.x < UNITS) {
            const int i = threadIdx.x;
            // fast gates: __expf (MUFU) + approx division
            float ar = gir + sums[i]      + bsh[i];
            float az = giz + sums[16 + i] + bsh[16 + i];
            float rg = __fdividef(1.f, 1.f + __expf(-ar));
            float zg = __fdividef(1.f, 1.f + __expf(-az));
            float an = gin + rg * (sums[32 + i] + bsh[32 + i]);
            float en = __expf(-2.f * an);
            float ng = __fdividef(1.f - en, 1.f + en);   // tanh(an)
            hn = (1.f - zg) * ng + zg * hprev;
            hprev = hn;
            __stcg(&g_h[dir][(s + 1) & 1][u0 + i], hn);
        }
        __syncthreads();                // h stores ordered before the release
        if (threadIdx.x == 0) {
            red_rel_add(cnt_p);         // release-REDG: publish h + count
        }
        // out stores AFTER the publish: off the release drain set, never
        // read in-kernel; kernel exit orders them for the harness.
        if (threadIdx.x < UNITS && s >= 1) {
            const int u = u0 + threadIdx.x;
            out[(size_t)HID + (size_t)t * (2 * HID) + dir * HID + u] = hn;
            if (dir == 1 && t == 0) out[u] = hn;    // h_b = hs_b[0]
        }
    }
}

// ---------------------------------------------------------------------------
// launch
// ---------------------------------------------------------------------------
extern "C" void kernel_launch(void* const* d_in, const int* in_sizes, int n_in,
                              void* d_out, int out_size) {
    const void*  tokens = d_in[0];
    const float* emb    = (const float*)d_in[1];
    const float* w_ih   = (const float*)d_in[2];
    const float* w_hh   = (const float*)d_in[3];
    const float* b_ih   = (const float*)d_in[4];
    const float* b_hh   = (const float*)d_in[5];
    float* out = (float*)d_out;

    const int smem_bytes = (RSM * 8 * HID + 2 * RPC + 16) * (int)sizeof(float);
    cudaFuncSetAttribute(gru_seq_kernel,
                         cudaFuncAttributeMaxDynamicSharedMemorySize,
                         smem_bytes);

    dim3 ggrid(GATES / BN, (NROWS + BM - 1) / BM);
    gi_gemm_kernel<<<ggrid, 256>>>(tokens, emb, w_ih, b_ih);

    gru_seq_kernel<<<NCTA, GT, smem_bytes>>>(w_hh, b_hh, out);
}

// round 13
// speedup vs baseline: 1.4054x; 1.0889x over previous
#include <cuda_runtime.h>
#include <cstdint>

// ---------------------------------------------------------------------------
// EncoderGRU: bidirectional GRU, SEQ=4096, HIDDEN=EMBED=1024.
//
//   Phase 1+2 (one kernel): GI[t] = w_ih @ emb[tok[t]] + b_ih, fp32 SIMT GEMM,
//            inline token prep + recurrent-state reset by block (0,0).
//   Phase 3: persistent kernel, 128 CTAs (64 fwd / 64 bwd), each CTA owns 16
//            hidden units (48 w_hh rows; 4/warp in registers, 2/warp in smem).
//            Sync protocol: r12-proven: producer red.release.gpu after CTA
//            barrier; consumer ld.acquire.gpu poll + clock-spin backoff.
//            NEW this round:
//              - matvec uses packed fma.rn.f32x2 (2 fp32 MACs per issue,
//                PTX-only on sm_10x): FFMA floor 768 -> 384 cyc/step.
//              - spin quantum 350 -> 180 cyc (the quantum rides the
//                worst-of-64-CTAs detect tail on the critical path).
// ---------------------------------------------------------------------------

#define VOCAB   50257
#define HID     1024
#define SEQ     4096
#define NROWS   (SEQ + 2)       // 4098: +SOS row, +EOS row
#define GATES   3072

#define NCTA    128             // persistent grid (1 CTA/SM)
#define UNITS   16              // hidden units per CTA (64 CTAs/dir * 16 = 1024)
#define RPC     48              // weight rows per CTA (3 gates * 16 units)
#define GT      256             // threads in recurrent kernel
#define RPW     6               // rows per warp (8 warps * 6 = 48)
#define RREG    4               // rows per warp held in registers
#define RSM     2               // rows per warp streamed from smem (RPW-RREG)

// ---- global scratch (allocation-free: __device__ globals) ----
__device__ __align__(16)  float g_GI[(size_t)NROWS * GATES];    // ~50 MB
__device__ __align__(16)  float g_h[2][2][HID];                 // [dir][buf][unit]
__device__ __align__(128) int   g_cnt[2][32];                   // one 128B line per dir

// acquire-load: ordering + data in one instruction (pairs with red.release)
__device__ __forceinline__ int ld_acq(const int* p) {
    int v;
    asm volatile("ld.acquire.gpu.global.b32 %0, [%1];"
                 : "=r"(v) : "l"(p) : "memory");
    return v;
}
// release-reduction: publishes +1 with release semantics (cumulative through
// the preceding bar.sync -> covers the CTA's prior h stores)
__device__ __forceinline__ void red_rel_add(int* p) {
    asm volatile("red.release.gpu.global.add.u32 [%0], 1;"
                 :: "l"(p) : "memory");
}
// packed dual-fp32 FMA: d = a*b + d (elementwise on 2 packed floats)
__device__ __forceinline__ void fma_f32x2(unsigned long long& d,
                                          unsigned long long a,
                                          unsigned long long b) {
    asm("fma.rn.f32x2 %0, %1, %2, %3;" : "=l"(d) : "l"(a), "l"(b), "l"(d));
}
__device__ __forceinline__ float f32x2_hsum(unsigned long long v) {
    float lo, hi;
    asm("mov.b64 {%0, %1}, %2;" : "=f"(lo), "=f"(hi) : "l"(v));
    return lo + hi;
}

// Calibrated busy-wait: no memory traffic, bounded duration (SM clock cycles).
__device__ __forceinline__ void spin_cycles(long long n) {
    long long lim = clock64() + n;
    while (clock64() < lim) { }
}

// ---------------------------------------------------------------------------
// Phase 1+2: GI GEMM with inline token prep + state reset.
// C[m][n] = sum_k emb[tok[m]][k] * w_ih[n][k] + b_ih[n]
// BM=BN=128, BK=8, 256 threads, 8x8 microtile per thread.
// ---------------------------------------------------------------------------
#define BM 128
#define BN 128
#define BK 8

__global__ void __launch_bounds__(256) gi_gemm_kernel(
    const void*  __restrict__ tok_raw,
    const float* __restrict__ emb,
    const float* __restrict__ w_ih,
    const float* __restrict__ b_ih) {

    __shared__ float As[BK][BM];
    __shared__ float Bs[BK][BN];
    __shared__ int   mode64_sh;

    const int tid  = threadIdx.x;
    const int m0   = blockIdx.y * BM;
    const int n0   = blockIdx.x * BN;
    const int lrow = tid >> 1;          // 0..127
    const int lk   = (tid & 1) * 4;     // 0 or 4
    const int tx   = tid & 15;
    const int ty   = tid >> 4;

    // state reset (fresh every launch / graph replay) -- block (0,0) only
    if (blockIdx.x == 0 && blockIdx.y == 0) {
        for (int i = tid; i < 2 * 2 * HID; i += 256) ((float*)g_h)[i] = 0.f;
        if (tid < 64) ((int*)g_cnt)[tid] = 0;
    }

    // token dtype detection (per block; 8 loads, trivial)
    if (tid == 0) {
        // Genuine int64 tokens: every value < VOCAB (high word 0).
        // int32 data misread as int64: some 64-bit word >= VOCAB w.h.p.
        const unsigned long long* p = (const unsigned long long*)tok_raw;
        int m = 1;
        #pragma unroll
        for (int i = 0; i < 8; i++)
            if (p[i] >= (unsigned long long)VOCAB) m = 0;
        mode64_sh = m;
    }
    __syncthreads();
    const int mode64 = mode64_sh;

    // inline token fetch for this block's A row
    const int m = m0 + lrow;
    const float* arow_ptr = nullptr;
    if (m < NROWS) {
        int tok;
        if (m == SEQ)          tok = 0;   // SOS
        else if (m == SEQ + 1) tok = 1;   // EOS
        else tok = mode64 ? (int)((const long long*)tok_raw)[m]
                          : ((const int*)tok_raw)[m];
        arow_ptr = emb + (size_t)tok * HID;
    }
    const float* brow_ptr = w_ih + (size_t)(n0 + lrow) * HID;

    float acc[8][8];
    #pragma unroll
    for (int i = 0; i < 8; i++)
        #pragma unroll
        for (int j = 0; j < 8; j++) acc[i][j] = 0.f;

    for (int k0 = 0; k0 < HID; k0 += BK) {
        float4 a4 = make_float4(0.f, 0.f, 0.f, 0.f);
        if (arow_ptr) a4 = *(const float4*)(arow_ptr + k0 + lk);
        float4 b4 = *(const float4*)(brow_ptr + k0 + lk);
        As[lk + 0][lrow] = a4.x; As[lk + 1][lrow] = a4.y;
        As[lk + 2][lrow] = a4.z; As[lk + 3][lrow] = a4.w;
        Bs[lk + 0][lrow] = b4.x; Bs[lk + 1][lrow] = b4.y;
        Bs[lk + 2][lrow] = b4.z; Bs[lk + 3][lrow] = b4.w;
        __syncthreads();

        #pragma unroll
        for (int kk = 0; kk < BK; kk++) {
            float ra[8], rb[8];
            *(float4*)&ra[0] = *(const float4*)&As[kk][ty * 8];
            *(float4*)&ra[4] = *(const float4*)&As[kk][ty * 8 + 4];
            *(float4*)&rb[0] = *(const float4*)&Bs[kk][tx * 8];
            *(float4*)&rb[4] = *(const float4*)&Bs[kk][tx * 8 + 4];
            #pragma unroll
            for (int i = 0; i < 8; i++)
                #pragma unroll
                for (int j = 0; j < 8; j++)
                    acc[i][j] += ra[i] * rb[j];
        }
        __syncthreads();
    }

    float bias[8];
    *(float4*)&bias[0] = *(const float4*)(b_ih + n0 + tx * 8);
    *(float4*)&bias[4] = *(const float4*)(b_ih + n0 + tx * 8 + 4);

    #pragma unroll
    for (int i = 0; i < 8; i++) {
        int mm = m0 + ty * 8 + i;
        if (mm < NROWS) {
            float* gp = g_GI + (size_t)mm * GATES + n0 + tx * 8;
            float4 v0 = make_float4(acc[i][0] + bias[0], acc[i][1] + bias[1],
                                    acc[i][2] + bias[2], acc[i][3] + bias[3]);
            float4 v1 = make_float4(acc[i][4] + bias[4], acc[i][5] + bias[5],
                                    acc[i][6] + bias[6], acc[i][7] + bias[7]);
            *(float4*)gp       = v0;
            *(float4*)(gp + 4) = v1;
        }
    }
}

// ---------------------------------------------------------------------------
// Phase 3: persistent recurrent kernel (f32x2 matvec).
// Weight rows per warp: rows 0..3 in registers, rows 4..5 in smem.
// Global row for local row rr (0..47): ((rr>>4)<<10) + u0 + (rr&15).
// All weight/h accesses are 16B = ulonglong2 = 2 packed f32x2 operands.
// ---------------------------------------------------------------------------
__global__ void __launch_bounds__(GT, 1) gru_seq_kernel(
    const float* __restrict__ w_hh,
    const float* __restrict__ b_hh,
    float* __restrict__ out) {

    extern __shared__ float smem[];
    float* wsh  = smem;                 // 16 rows (2/warp) * HID
    float* bsh  = smem + (RSM * 8) * HID;   // RPC biases
    float* sums = bsh + RPC;            // RPC partial sums

    const int cta  = blockIdx.x;
    const int dir  = cta >> 6;          // 0 = forward, 1 = backward
    const int lcta = cta & 63;
    const int u0   = lcta * UNITS;
    const int warp = threadIdx.x >> 5;
    const int lane = threadIdx.x & 31;

    // --- smem rows: local rows {w*6+4, w*6+5} stored at smem row (w*2 + sub)
    for (int i = threadIdx.x; i < RSM * 8 * HID; i += GT) {
        int mrow = i >> 10;             // 0..15
        int c    = i & (HID - 1);
        int rr   = (mrow >> 1) * RPW + RREG + (mrow & 1);
        int grow = ((rr >> 4) << 10) + u0 + (rr & 15);
        wsh[i] = w_hh[(size_t)grow * HID + c];
    }
    if (threadIdx.x < RPC) {
        int rr = threadIdx.x;
        bsh[rr] = b_hh[((rr >> 4) << 10) + u0 + (rr & 15)];
    }

    // --- register rows: warp's local rows 0..3, this lane's 32 columns,
    // held as ulonglong2 (= 4 floats = 2 f32x2 operands each)
    ulonglong2 wreg[RREG][8];
    #pragma unroll
    for (int r = 0; r < RREG; r++) {
        const int rr   = warp * RPW + r;
        const int grow = ((rr >> 4) << 10) + u0 + (rr & 15);
        const float* gw = w_hh + (size_t)grow * HID + lane * 4;
        #pragma unroll
        for (int j = 0; j < 8; j++)
            wreg[r][j] = *(const ulonglong2*)(gw + j * 128);
    }
    __syncthreads();

    const float* wp = wsh + (warp * RSM) * HID + lane * 4;  // smem rows 4..5
    int* cnt_p = &g_cnt[dir][0];

    float hprev = 0.f;                  // held by threads < UNITS only

    for (int s = 0; s <= SEQ; s++) {
        const int t     = dir ? (SEQ - s) : (s - 1);
        const int girow = (s == 0) ? (SEQ + dir) : t;

        // gi prefetch (independent of h; overlaps the poll below)
        float gir = 0.f, giz = 0.f, gin = 0.f;
        if (threadIdx.x < UNITS) {
            const float* gp = g_GI + (size_t)girow * GATES + u0 + threadIdx.x;
            gir = __ldg(gp);
            giz = __ldg(gp + HID);
            gin = __ldg(gp + 2 * HID);
        }

        // Wait until all 64 CTAs of this direction finished step s-1.
        // EVERY thread polls with an ACQUIRE load (broadcast 4B sector);
        // ~180cyc spin backoff: the quantum rides the worst-of-64 tail.
        if (s > 0) {
            const int need = s << 6;    // 64 * s
            if (ld_acq(cnt_p) < need) {
                do { spin_cycles(180); } while (ld_acq(cnt_p) < need);
            }
        }

        // load broadcast h as packed pairs (L2)
        const ulonglong2* hp = (const ulonglong2*)(&g_h[dir][s & 1][0]) + lane;
        ulonglong2 h2[8];
        #pragma unroll
        for (int j = 0; j < 8; j++) h2[j] = __ldcg(hp + 32 * j);

        // 6 dot products per warp in packed f32x2:
        // rows 0..3 from registers, rows 4..5 from smem
        unsigned long long accp[RPW] = {0ull, 0ull, 0ull, 0ull, 0ull, 0ull};
        #pragma unroll
        for (int j = 0; j < 8; j++) {
            const ulonglong2 hv = h2[j];
            #pragma unroll
            for (int r = 0; r < RREG; r++) {
                fma_f32x2(accp[r], wreg[r][j].x, hv.x);
                fma_f32x2(accp[r], wreg[r][j].y, hv.y);
            }
            #pragma unroll
            for (int r = 0; r < RSM; r++) {
                const ulonglong2 wv = *(const ulonglong2*)(wp + r * HID + j * 128);
                fma_f32x2(accp[RREG + r], wv.x, hv.x);
                fma_f32x2(accp[RREG + r], wv.y, hv.y);
            }
        }
        #pragma unroll
        for (int r = 0; r < RPW; r++) {
            float v = f32x2_hsum(accp[r]);
            v += __shfl_xor_sync(0xffffffffu, v, 16);
            v += __shfl_xor_sync(0xffffffffu, v, 8);
            v += __shfl_xor_sync(0xffffffffu, v, 4);
            v += __shfl_xor_sync(0xffffffffu, v, 2);
            v += __shfl_xor_sync(0xffffffffu, v, 1);
            if (lane == 0) sums[warp * RPW + r] = v;
        }
        __syncthreads();                // sums ready

        float hn = 0.f;
        if (threadIdx.x < UNITS) {
            const int i = threadIdx.x;
            // fast gates: __expf (MUFU) + approx division
            float ar = gir + sums[i]      + bsh[i];
            float az = giz + sums[16 + i] + bsh[16 + i];
            float rg = __fdividef(1.f, 1.f + __expf(-ar));
            float zg = __fdividef(1.f, 1.f + __expf(-az));
            float an = gin + rg * (sums[32 + i] + bsh[32 + i]);
            float en = __expf(-2.f * an);
            float ng = __fdividef(1.f - en, 1.f + en);   // tanh(an)
            hn = (1.f - zg) * ng + zg * hprev;
            hprev = hn;
            __stcg(&g_h[dir][(s + 1) & 1][u0 + i], hn);
        }
        __syncthreads();                // h stores ordered before the release
        if (threadIdx.x == 0) {
            red_rel_add(cnt_p);         // release-REDG: publish h + count
        }
        // out stores AFTER the publish: off the release drain set, never
        // read in-kernel; kernel exit orders them for the harness.
        if (threadIdx.x < UNITS && s >= 1) {
            const int u = u0 + threadIdx.x;
            out[(size_t)HID + (size_t)t * (2 * HID) + dir * HID + u] = hn;
            if (dir == 1 && t == 0) out[u] = hn;    // h_b = hs_b[0]
        }
    }
}

// ---------------------------------------------------------------------------
// launch
// ---------------------------------------------------------------------------
extern "C" void kernel_launch(void* const* d_in, const int* in_sizes, int n_in,
                              void* d_out, int out_size) {
    const void*  tokens = d_in[0];
    const float* emb    = (const float*)d_in[1];
    const float* w_ih   = (const float*)d_in[2];
    const float* w_hh   = (const float*)d_in[3];
    const float* b_ih   = (const float*)d_in[4];
    const float* b_hh   = (const float*)d_in[5];
    float* out = (float*)d_out;

    const int smem_bytes = (RSM * 8 * HID + 2 * RPC + 16) * (int)sizeof(float);
    cudaFuncSetAttribute(gru_seq_kernel,
                         cudaFuncAttributeMaxDynamicSharedMemorySize,
                         smem_bytes);

    dim3 ggrid(GATES / BN, (NROWS + BM - 1) / BM);
    gi_gemm_kernel<<<ggrid, 256>>>(tokens, emb, w_ih, b_ih);

    gru_seq_kernel<<<NCTA, GT, smem_bytes>>>(w_hh, b_hh, out);
}